// round 13
// baseline (speedup 1.0000x reference)
#include <cuda_runtime.h>
#include <cuda_fp16.h>
#include <cstdint>

#define NN 50000
#define NE 800000
#define NG 64
#define MAXF 128
#define SCAN_BLK 256
#define NBLK ((NN + SCAN_BLK - 1) / SCAN_BLK)   // 196

typedef unsigned long long ull;

// ---------------- scratch (device globals; no runtime allocation) ----------------
__device__ __align__(16) float g_bufA[NN * MAXF];
__device__ __align__(16) __half g_h16[NN * MAXF];     // fp16 H (all layers)
__device__ int   g_src[NE];
__device__ int   g_dst[NE];
__device__ ull   g_edge[NE];     // CSR-permuted (src | norm<<32)
__device__ int   g_count[NN];
__device__ int   g_rowptr[NN];   // bucket base (end = base + count)
__device__ int   g_fill[NN];
__device__ float g_deg[NN];
__device__ float g_dinv[NN];
__device__ float g_invdeg[NN];
__device__ __align__(16) float g_pool[NG * 32];
__device__ float g_cnt[NG];
__device__ unsigned int g_maxbits;
__device__ unsigned int g_oddOr;
__device__ int g_total;

// ---------------- packed f32x2 helpers ----------------
__device__ __forceinline__ ull pack2(float x, float y) {
    ull r; asm("mov.b64 %0, {%1,%2};" : "=l"(r) : "f"(x), "f"(y)); return r;
}
__device__ __forceinline__ void unpack2(ull v, float& x, float& y) {
    asm("mov.b64 {%0,%1}, %2;" : "=f"(x), "=f"(y) : "l"(v));
}
__device__ __forceinline__ void ffma2(ull& c, ull a, ull b) {
    asm("fma.rn.f32x2 %0, %1, %2, %0;" : "+l"(c) : "l"(a), "l"(b));
}

// ---------------- init + fast dtype detection ----------------
__global__ void k_init(const unsigned int* __restrict__ ei32) {
    int i = blockIdx.x * blockDim.x + threadIdx.x;
    if (i < NN) { g_deg[i] = 0.f; g_count[i] = 0; g_fill[i] = 0; }
    if (i < NG * 32) g_pool[i] = 0.f;
    if (i < NG) g_cnt[i] = 0.f;
    if (i == 0) { g_maxbits = 0u; g_oddOr = 0u; g_total = 0; }
    if (blockIdx.x == 0) {
        __syncthreads();
        unsigned int v = 0;
        for (int t = threadIdx.x; t < 8192; t += blockDim.x)
            v |= ei32[2 * t + 1];
#pragma unroll
        for (int o = 16; o; o >>= 1) v |= __shfl_xor_sync(0xffffffffu, v, o);
        if ((threadIdx.x & 31) == 0 && v) atomicOr(&g_oddOr, v);
    }
}

// ---------------- fused per-edge pass: decode, max(ea), raw deg, count ----------------
__global__ void k_prep(const void* __restrict__ ei, const float* __restrict__ ea) {
    bool is64 = (g_oddOr == 0u);
    const long long* p64 = (const long long*)ei;
    const int* p32 = (const int*)ei;
    float m = 0.f;
    for (int e = blockIdx.x * blockDim.x + threadIdx.x; e < NE;
         e += gridDim.x * blockDim.x) {
        int s, d;
        if (is64) { s = (int)p64[e]; d = (int)p64[NE + e]; }
        else      { s = p32[e];      d = p32[NE + e]; }
        g_src[e] = s;
        g_dst[e] = d;
        float a = ea[e];
        m = fmaxf(m, a);
        atomicAdd(&g_deg[d], a);
        atomicAdd(&g_count[d], 1);
    }
#pragma unroll
    for (int o = 16; o; o >>= 1) m = fmaxf(m, __shfl_xor_sync(0xffffffffu, m, o));
    if ((threadIdx.x & 31) == 0) atomicMax(&g_maxbits, __float_as_uint(m));
}

// ---------------- single-pass bucket allocation + node factors ----------------
__global__ void k_scanA() {
    __shared__ int wsum[SCAN_BLK / 32];
    __shared__ int sbase;
    int i = blockIdx.x * SCAN_BLK + threadIdx.x;
    int c = (i < NN) ? g_count[i] : 0;
    int lane = threadIdx.x & 31, wid = threadIdx.x >> 5;
    int v = c;
#pragma unroll
    for (int o = 1; o < 32; o <<= 1) {
        int u = __shfl_up_sync(0xffffffffu, v, o);
        if (lane >= o) v += u;
    }
    if (lane == 31) wsum[wid] = v;
    __syncthreads();
    if (wid == 0) {
        int w = (lane < SCAN_BLK / 32) ? wsum[lane] : 0;
#pragma unroll
        for (int o = 1; o < SCAN_BLK / 32; o <<= 1) {
            int u = __shfl_up_sync(0xffffffffu, w, o);
            if (lane >= o) w += u;
        }
        if (lane < SCAN_BLK / 32) wsum[lane] = w;
    }
    __syncthreads();
    if (threadIdx.x == 0) sbase = atomicAdd(&g_total, wsum[SCAN_BLK / 32 - 1]);
    __syncthreads();
    if (i < NN) {
        int excl = v - c + (wid > 0 ? wsum[wid - 1] : 0);
        g_rowptr[i] = sbase + excl;
        float invmax = 1.f / __uint_as_float(g_maxbits);
        float d = fmaf(g_deg[i], invmax, 1.f);
        g_dinv[i] = rsqrtf(d);
        g_invdeg[i] = 1.f / d;
    }
}

// ---------------- fill CSR: one packed 8B store per edge ----------------
__global__ void k_fill(const float* __restrict__ ea) {
    int e = blockIdx.x * blockDim.x + threadIdx.x;
    if (e >= NE) return;
    int s = g_src[e], d = g_dst[e];
    float invmax = 1.f / __uint_as_float(g_maxbits);
    float norm = g_dinv[s] * (ea[e] * invmax) * g_dinv[d];
    int pos = g_rowptr[d] + atomicAdd(&g_fill[d], 1);
    g_edge[pos] = (ull)(unsigned int)s | ((ull)__float_as_uint(norm) << 32);
}

// ---------------- 128xN-tiled fp32 GEMM, fp16 H output (no launch bounds) ----------------
template <int BN, int TN>
__global__ void k_gemm(const float* __restrict__ Aext, int useBufA,
                       const float* __restrict__ W, int M, int K, int reluIn) {
    __shared__ float As[16][132];
    __shared__ float Bs[16][BN + 4];
    const float* A = useBufA ? g_bufA : Aext;

    int tid = threadIdx.x;
    int tr = tid >> 4;
    int tc = tid & 15;
    int rowBase = blockIdx.y * 128;

    ull acc2[8][TN / 2];
#pragma unroll
    for (int i = 0; i < 8; i++)
#pragma unroll
        for (int j = 0; j < TN / 2; j++) acc2[i][j] = 0ull;

    for (int kt = 0; kt < K; kt += 16) {
#pragma unroll
        for (int idx = tid; idx < 512; idx += 256) {
            int r = idx >> 2;
            int c4 = (idx & 3) * 4;
            int ar = rowBase + r;
            float4 v = make_float4(0.f, 0.f, 0.f, 0.f);
            if (ar < M) v = *(const float4*)(A + (size_t)ar * K + kt + c4);
            if (reluIn) {
                v.x = fmaxf(v.x, 0.f); v.y = fmaxf(v.y, 0.f);
                v.z = fmaxf(v.z, 0.f); v.w = fmaxf(v.w, 0.f);
            }
            As[c4 + 0][r] = v.x; As[c4 + 1][r] = v.y;
            As[c4 + 2][r] = v.z; As[c4 + 3][r] = v.w;
        }
        constexpr int F4R = BN / 4;
#pragma unroll
        for (int idx = tid; idx < 16 * F4R; idx += 256) {
            int r = idx / F4R;
            int c = (idx % F4R) * 4;
            float4 v = *(const float4*)(W + (size_t)(kt + r) * BN + c);
            *(float4*)&Bs[r][c] = v;
        }
        __syncthreads();

#pragma unroll
        for (int kk = 0; kk < 16; kk++) {
            float a[8];
            *(float4*)&a[0] = *(const float4*)&As[kk][tr * 8];
            *(float4*)&a[4] = *(const float4*)&As[kk][tr * 8 + 4];
            ull bp[TN / 2];
#pragma unroll
            for (int j = 0; j < TN / 2; j++)
                bp[j] = *(const ull*)&Bs[kk][tc * TN + 2 * j];
#pragma unroll
            for (int i = 0; i < 8; i++) {
                ull aa = pack2(a[i], a[i]);
#pragma unroll
                for (int j = 0; j < TN / 2; j++) ffma2(acc2[i][j], aa, bp[j]);
            }
        }
        __syncthreads();
    }

#pragma unroll
    for (int i = 0; i < 8; i++) {
        int r = rowBase + tr * 8 + i;
        if (r >= M) continue;
        float o[TN];
#pragma unroll
        for (int j = 0; j < TN / 2; j++) unpack2(acc2[i][j], o[2 * j], o[2 * j + 1]);
        __half hh[TN];
#pragma unroll
        for (int j = 0; j < TN; j++) hh[j] = __float2half_rn(o[j]);
        char* dst = (char*)(g_h16 + (size_t)r * BN + tc * TN);
        if (TN == 8)      *(uint4*)dst = *(uint4*)hh;
        else if (TN == 4) *(uint2*)dst = *(uint2*)hh;
        else              *(unsigned int*)dst = *(unsigned int*)hh;
    }
}

// ---------------- fp16 gather: AGG(fp32) = H16[n]*invdeg + bias + sum norm*H16[src] ----------------
// VEC = chunks of 8 halves (16B) per node row; each thread owns 8 features.
template <int VEC, int SHIFT>
__global__ void k_gather16(const float* __restrict__ bias) {
    int t = blockIdx.x * blockDim.x + threadIdx.x;
    if (t >= NN * VEC) return;
    int n = t >> SHIFT;
    int j = t & (VEC - 1);
    int beg = g_rowptr[n];
    int end = beg + g_count[n];
    const uint4* __restrict__ H = (const uint4*)g_h16;
    const ull* __restrict__ edge = g_edge;

    float acc[8];
    {
        float id = g_invdeg[n];
        uint4 hv = H[(size_t)n * VEC + j];
        const __half2* h2 = (const __half2*)&hv;
        const float* b = bias + j * 8;
#pragma unroll
        for (int q = 0; q < 4; q++) {
            float2 f = __half22float2(h2[q]);
            acc[2 * q + 0] = fmaf(f.x, id, b[2 * q + 0]);
            acc[2 * q + 1] = fmaf(f.y, id, b[2 * q + 1]);
        }
    }

    int k = beg;
    for (; k + 4 <= end; k += 4) {
        ull e0 = edge[k], e1 = edge[k + 1], e2 = edge[k + 2], e3 = edge[k + 3];
        uint4 v0 = H[(size_t)(unsigned int)e0 * VEC + j];
        uint4 v1 = H[(size_t)(unsigned int)e1 * VEC + j];
        uint4 v2 = H[(size_t)(unsigned int)e2 * VEC + j];
        uint4 v3 = H[(size_t)(unsigned int)e3 * VEC + j];
        float n0 = __uint_as_float((unsigned int)(e0 >> 32));
        float n1 = __uint_as_float((unsigned int)(e1 >> 32));
        float n2 = __uint_as_float((unsigned int)(e2 >> 32));
        float n3 = __uint_as_float((unsigned int)(e3 >> 32));
        const __half2* p0 = (const __half2*)&v0;
        const __half2* p1 = (const __half2*)&v1;
        const __half2* p2 = (const __half2*)&v2;
        const __half2* p3 = (const __half2*)&v3;
#pragma unroll
        for (int q = 0; q < 4; q++) {
            float2 f0 = __half22float2(p0[q]);
            float2 f1 = __half22float2(p1[q]);
            float2 f2 = __half22float2(p2[q]);
            float2 f3 = __half22float2(p3[q]);
            acc[2 * q + 0] = fmaf(n0, f0.x, acc[2 * q + 0]);
            acc[2 * q + 1] = fmaf(n0, f0.y, acc[2 * q + 1]);
            acc[2 * q + 0] = fmaf(n1, f1.x, acc[2 * q + 0]);
            acc[2 * q + 1] = fmaf(n1, f1.y, acc[2 * q + 1]);
            acc[2 * q + 0] = fmaf(n2, f2.x, acc[2 * q + 0]);
            acc[2 * q + 1] = fmaf(n2, f2.y, acc[2 * q + 1]);
            acc[2 * q + 0] = fmaf(n3, f3.x, acc[2 * q + 0]);
            acc[2 * q + 1] = fmaf(n3, f3.y, acc[2 * q + 1]);
        }
    }
    for (; k < end; k++) {
        ull e0 = edge[k];
        float nm = __uint_as_float((unsigned int)(e0 >> 32));
        uint4 v0 = H[(size_t)(unsigned int)e0 * VEC + j];
        const __half2* p0 = (const __half2*)&v0;
#pragma unroll
        for (int q = 0; q < 4; q++) {
            float2 f0 = __half22float2(p0[q]);
            acc[2 * q + 0] = fmaf(nm, f0.x, acc[2 * q + 0]);
            acc[2 * q + 1] = fmaf(nm, f0.y, acc[2 * q + 1]);
        }
    }

    float* dst = g_bufA + ((size_t)n * VEC + j) * 8;
    *(float4*)dst = *(float4*)&acc[0];
    *(float4*)(dst + 4) = *(float4*)&acc[4];
}

// ---------------- layer-3 fp16 gather fused with relu + mean-pool ----------------
// 32 features = 4 chunks of 8 halves; each thread owns 8 features.
__global__ void k_gather_pool16(const float* __restrict__ bias,
                                const void* __restrict__ batch) {
    int t = blockIdx.x * blockDim.x + threadIdx.x;
    if (t >= NN * 4) return;
    int n = t >> 2;
    int j = t & 3;
    int beg = g_rowptr[n];
    int end = beg + g_count[n];
    const uint4* __restrict__ H = (const uint4*)g_h16;
    const ull* __restrict__ edge = g_edge;

    float acc[8];
    {
        float id = g_invdeg[n];
        uint4 hv = H[(size_t)n * 4 + j];
        const __half2* h2 = (const __half2*)&hv;
        const float* b = bias + j * 8;
#pragma unroll
        for (int q = 0; q < 4; q++) {
            float2 f = __half22float2(h2[q]);
            acc[2 * q + 0] = fmaf(f.x, id, b[2 * q + 0]);
            acc[2 * q + 1] = fmaf(f.y, id, b[2 * q + 1]);
        }
    }

    int k = beg;
    for (; k + 4 <= end; k += 4) {
        ull e0 = edge[k], e1 = edge[k + 1], e2 = edge[k + 2], e3 = edge[k + 3];
        uint4 v0 = H[(size_t)(unsigned int)e0 * 4 + j];
        uint4 v1 = H[(size_t)(unsigned int)e1 * 4 + j];
        uint4 v2 = H[(size_t)(unsigned int)e2 * 4 + j];
        uint4 v3 = H[(size_t)(unsigned int)e3 * 4 + j];
        float n0 = __uint_as_float((unsigned int)(e0 >> 32));
        float n1 = __uint_as_float((unsigned int)(e1 >> 32));
        float n2 = __uint_as_float((unsigned int)(e2 >> 32));
        float n3 = __uint_as_float((unsigned int)(e3 >> 32));
        const __half2* p0 = (const __half2*)&v0;
        const __half2* p1 = (const __half2*)&v1;
        const __half2* p2 = (const __half2*)&v2;
        const __half2* p3 = (const __half2*)&v3;
#pragma unroll
        for (int q = 0; q < 4; q++) {
            float2 f0 = __half22float2(p0[q]);
            float2 f1 = __half22float2(p1[q]);
            float2 f2 = __half22float2(p2[q]);
            float2 f3 = __half22float2(p3[q]);
            acc[2 * q + 0] = fmaf(n0, f0.x, acc[2 * q + 0]);
            acc[2 * q + 1] = fmaf(n0, f0.y, acc[2 * q + 1]);
            acc[2 * q + 0] = fmaf(n1, f1.x, acc[2 * q + 0]);
            acc[2 * q + 1] = fmaf(n1, f1.y, acc[2 * q + 1]);
            acc[2 * q + 0] = fmaf(n2, f2.x, acc[2 * q + 0]);
            acc[2 * q + 1] = fmaf(n2, f2.y, acc[2 * q + 1]);
            acc[2 * q + 0] = fmaf(n3, f3.x, acc[2 * q + 0]);
            acc[2 * q + 1] = fmaf(n3, f3.y, acc[2 * q + 1]);
        }
    }
    for (; k < end; k++) {
        ull e0 = edge[k];
        float nm = __uint_as_float((unsigned int)(e0 >> 32));
        uint4 v0 = H[(size_t)(unsigned int)e0 * 4 + j];
        const __half2* p0 = (const __half2*)&v0;
#pragma unroll
        for (int q = 0; q < 4; q++) {
            float2 f0 = __half22float2(p0[q]);
            acc[2 * q + 0] = fmaf(nm, f0.x, acc[2 * q + 0]);
            acc[2 * q + 1] = fmaf(nm, f0.y, acc[2 * q + 1]);
        }
    }

    int g;
    if (g_oddOr == 0u) g = (int)((const long long*)batch)[n];
    else               g = ((const int*)batch)[n];
    float* p = &g_pool[g * 32 + j * 8];
#pragma unroll
    for (int q = 0; q < 8; q++) atomicAdd(p + q, fmaxf(acc[q], 0.f));
    if (j == 0) atomicAdd(&g_cnt[g], 1.f);
}

// ---------------- head ----------------
__global__ void k_out(const float* __restrict__ Wl, const float* __restrict__ bl,
                      float* __restrict__ out) {
    __shared__ float pooled[32];
    int g = blockIdx.x;
    if (threadIdx.x < 32) {
        float c = g_cnt[g];
        pooled[threadIdx.x] = g_pool[g * 32 + threadIdx.x] / fmaxf(c, 1.f);
    }
    __syncthreads();
    int o = threadIdx.x;  // 768 threads
    float acc = bl[o];
#pragma unroll
    for (int c = 0; c < 32; c++) acc = fmaf(pooled[c], Wl[c * 768 + o], acc);
    out[(size_t)g * 768 + o] = acc;
}

// ---------------- launch (fork/join: CSR build || layer-1 GEMM) ----------------
extern "C" void kernel_launch(void* const* d_in, const int* in_sizes, int n_in,
                              void* d_out, int out_size) {
    const float* x = (const float*)d_in[0];
    const void* ei = d_in[1];
    const float* ea = (const float*)d_in[2];
    const void* batch = d_in[3];
    const float* W1 = (const float*)d_in[4];
    const float* b1 = (const float*)d_in[5];
    const float* W2 = (const float*)d_in[6];
    const float* b2 = (const float*)d_in[7];
    const float* W3 = (const float*)d_in[8];
    const float* b3 = (const float*)d_in[9];
    const float* Wl = (const float*)d_in[10];
    const float* bl = (const float*)d_in[11];
    float* out = (float*)d_out;

    static cudaStream_t s2 = nullptr;
    static cudaEvent_t evFork = nullptr, evJoin = nullptr;
    if (!s2) {
        cudaStreamCreateWithFlags(&s2, cudaStreamNonBlocking);
        cudaEventCreateWithFlags(&evFork, cudaEventDisableTiming);
        cudaEventCreateWithFlags(&evJoin, cudaEventDisableTiming);
    }
    cudaStream_t s0 = cudaStreamPerThread;

    // Fork: side stream runs layer-1 GEMM (depends only on x, W1) -> fp16 H.
    cudaEventRecord(evFork, s0);
    cudaStreamWaitEvent(s2, evFork, 0);
    {
        dim3 grid(1, (NN + 127) / 128);
        k_gemm<128, 8><<<grid, 256, 0, s2>>>(x, 0, W1, NN, 128, /*relu=*/0);
        cudaEventRecord(evJoin, s2);
    }

    // Main stream: CSR build chain.
    k_init<<<(NN + 255) / 256, 256, 0, s0>>>((const unsigned int*)ei);
    k_prep<<<512, 256, 0, s0>>>(ei, ea);
    k_scanA<<<NBLK, SCAN_BLK, 0, s0>>>();
    k_fill<<<(NE + 255) / 256, 256, 0, s0>>>(ea);

    // Join: gather-1 needs both H16 (s2) and CSR (s0).
    cudaStreamWaitEvent(s0, evJoin, 0);
    k_gather16<16, 4><<<(NN * 16 + 255) / 256, 256, 0, s0>>>(b1);

    // Layer 2: relu(bufA) @ W2 -> fp16 H; fp16 gather -> bufA
    {
        dim3 grid(1, (NN + 127) / 128);
        k_gemm<64, 4><<<grid, 256, 0, s0>>>(nullptr, 1, W2, NN, 128, /*relu=*/1);
        k_gather16<8, 3><<<(NN * 8 + 255) / 256, 256, 0, s0>>>(b2);
    }
    // Layer 3: relu(bufA) @ W3 -> fp16 H; fp16 gather fused with pool
    {
        dim3 grid(1, (NN + 127) / 128);
        k_gemm<32, 2><<<grid, 256, 0, s0>>>(nullptr, 1, W3, NN, 64, /*relu=*/1);
        k_gather_pool16<<<(NN * 4 + 255) / 256, 256, 0, s0>>>(b3, batch);
    }
    k_out<<<NG, 768, 0, s0>>>(Wl, bl, out);
}

// round 14
// speedup vs baseline: 1.0568x; 1.0568x over previous
#include <cuda_runtime.h>
#include <cuda_fp16.h>
#include <cstdint>

#define NN 50000
#define NE 800000
#define NG 64
#define MAXF 128
#define SCAN_BLK 256
#define NBLK ((NN + SCAN_BLK - 1) / SCAN_BLK)   // 196

typedef unsigned long long ull;

// ---------------- scratch (device globals; no runtime allocation) ----------------
__device__ __align__(16) float g_bufA[NN * MAXF];
__device__ __align__(16) float g_h[NN * MAXF];        // fp32 H (layer 3)
__device__ __align__(16) __half g_h16[NN * MAXF];     // fp16 H (layers 1,2)
__device__ int   g_src[NE];
__device__ int   g_dst[NE];
__device__ ull   g_edge[NE];     // CSR-permuted (src | norm<<32)
__device__ int   g_count[NN];
__device__ int   g_rowptr[NN];   // bucket base (end = base + count)
__device__ int   g_fill[NN];
__device__ float g_deg[NN];
__device__ float g_dinv[NN];
__device__ float g_invdeg[NN];
__device__ __align__(16) float g_pool[NG * 32];
__device__ float g_cnt[NG];
__device__ unsigned int g_maxbits;
__device__ unsigned int g_oddOr;
__device__ int g_total;

// ---------------- packed f32x2 helpers ----------------
__device__ __forceinline__ ull pack2(float x, float y) {
    ull r; asm("mov.b64 %0, {%1,%2};" : "=l"(r) : "f"(x), "f"(y)); return r;
}
__device__ __forceinline__ void unpack2(ull v, float& x, float& y) {
    asm("mov.b64 {%0,%1}, %2;" : "=f"(x), "=f"(y) : "l"(v));
}
__device__ __forceinline__ void ffma2(ull& c, ull a, ull b) {
    asm("fma.rn.f32x2 %0, %1, %2, %0;" : "+l"(c) : "l"(a), "l"(b));
}

// ---------------- init + fast dtype detection ----------------
__global__ void k_init(const unsigned int* __restrict__ ei32) {
    int i = blockIdx.x * blockDim.x + threadIdx.x;
    if (i < NN) { g_deg[i] = 0.f; g_count[i] = 0; g_fill[i] = 0; }
    if (i < NG * 32) g_pool[i] = 0.f;
    if (i < NG) g_cnt[i] = 0.f;
    if (i == 0) { g_maxbits = 0u; g_oddOr = 0u; g_total = 0; }
    if (blockIdx.x == 0) {
        __syncthreads();
        unsigned int v = 0;
        for (int t = threadIdx.x; t < 8192; t += blockDim.x)
            v |= ei32[2 * t + 1];
#pragma unroll
        for (int o = 16; o; o >>= 1) v |= __shfl_xor_sync(0xffffffffu, v, o);
        if ((threadIdx.x & 31) == 0 && v) atomicOr(&g_oddOr, v);
    }
}

// ---------------- fused per-edge pass: decode, max(ea), raw deg, count ----------------
__global__ void k_prep(const void* __restrict__ ei, const float* __restrict__ ea) {
    bool is64 = (g_oddOr == 0u);
    const long long* p64 = (const long long*)ei;
    const int* p32 = (const int*)ei;
    float m = 0.f;
    for (int e = blockIdx.x * blockDim.x + threadIdx.x; e < NE;
         e += gridDim.x * blockDim.x) {
        int s, d;
        if (is64) { s = (int)p64[e]; d = (int)p64[NE + e]; }
        else      { s = p32[e];      d = p32[NE + e]; }
        g_src[e] = s;
        g_dst[e] = d;
        float a = ea[e];
        m = fmaxf(m, a);
        atomicAdd(&g_deg[d], a);
        atomicAdd(&g_count[d], 1);
    }
#pragma unroll
    for (int o = 16; o; o >>= 1) m = fmaxf(m, __shfl_xor_sync(0xffffffffu, m, o));
    if ((threadIdx.x & 31) == 0) atomicMax(&g_maxbits, __float_as_uint(m));
}

// ---------------- single-pass bucket allocation + node factors ----------------
__global__ void k_scanA() {
    __shared__ int wsum[SCAN_BLK / 32];
    __shared__ int sbase;
    int i = blockIdx.x * SCAN_BLK + threadIdx.x;
    int c = (i < NN) ? g_count[i] : 0;
    int lane = threadIdx.x & 31, wid = threadIdx.x >> 5;
    int v = c;
#pragma unroll
    for (int o = 1; o < 32; o <<= 1) {
        int u = __shfl_up_sync(0xffffffffu, v, o);
        if (lane >= o) v += u;
    }
    if (lane == 31) wsum[wid] = v;
    __syncthreads();
    if (wid == 0) {
        int w = (lane < SCAN_BLK / 32) ? wsum[lane] : 0;
#pragma unroll
        for (int o = 1; o < SCAN_BLK / 32; o <<= 1) {
            int u = __shfl_up_sync(0xffffffffu, w, o);
            if (lane >= o) w += u;
        }
        if (lane < SCAN_BLK / 32) wsum[lane] = w;
    }
    __syncthreads();
    if (threadIdx.x == 0) sbase = atomicAdd(&g_total, wsum[SCAN_BLK / 32 - 1]);
    __syncthreads();
    if (i < NN) {
        int excl = v - c + (wid > 0 ? wsum[wid - 1] : 0);
        g_rowptr[i] = sbase + excl;
        float invmax = 1.f / __uint_as_float(g_maxbits);
        float d = fmaf(g_deg[i], invmax, 1.f);
        g_dinv[i] = rsqrtf(d);
        g_invdeg[i] = 1.f / d;
    }
}

// ---------------- fill CSR: one packed 8B store per edge ----------------
__global__ void k_fill(const float* __restrict__ ea) {
    int e = blockIdx.x * blockDim.x + threadIdx.x;
    if (e >= NE) return;
    int s = g_src[e], d = g_dst[e];
    float invmax = 1.f / __uint_as_float(g_maxbits);
    float norm = g_dinv[s] * (ea[e] * invmax) * g_dinv[d];
    int pos = g_rowptr[d] + atomicAdd(&g_fill[d], 1);
    g_edge[pos] = (ull)(unsigned int)s | ((ull)__float_as_uint(norm) << 32);
}

// ---------------- double-buffered 128xBN fp32 GEMM ----------------
// H = A @ W (no activation here; relu is applied by the producing gather).
// One __syncthreads per k-tile; tile t+1 global loads overlap tile t compute.
template <int BN, int TN, int STOREH>
__global__ void k_gemm(const float* __restrict__ Aext, int useBufA,
                       const float* __restrict__ W, int M, int K) {
    __shared__ float As[2][16][132];
    __shared__ float Bs[2][16][BN + 4];
    const float* A = useBufA ? g_bufA : Aext;

    int tid = threadIdx.x;
    int tr = tid >> 4;
    int tc = tid & 15;
    int rowBase = blockIdx.y * 128;

    constexpr int F4R = BN / 4;            // float4 chunks per B row
    constexpr int BCH = 16 * F4R;          // total B chunks (<= 512)
    constexpr int NB = (BCH + 255) / 256;  // B chunks per thread (1 or 2)

    ull acc2[8][TN / 2];
#pragma unroll
    for (int i = 0; i < 8; i++)
#pragma unroll
        for (int j = 0; j < TN / 2; j++) acc2[i][j] = 0ull;

    float4 aR[2];
    float4 bR[NB];

    auto loadTile = [&](int kt) {
#pragma unroll
        for (int u = 0; u < 2; u++) {
            int idx = tid + u * 256;
            int r = idx >> 2;
            int c4 = (idx & 3) * 4;
            int ar = rowBase + r;
            float4 v = make_float4(0.f, 0.f, 0.f, 0.f);
            if (ar < M) v = *(const float4*)(A + (size_t)ar * K + kt + c4);
            aR[u] = v;
        }
#pragma unroll
        for (int u = 0; u < NB; u++) {
            int idx = tid + u * 256;
            if (idx < BCH) {
                int r = idx / F4R;
                int c = (idx % F4R) * 4;
                bR[u] = *(const float4*)(W + (size_t)(kt + r) * BN + c);
            }
        }
    };
    auto storeTile = [&](int b) {
#pragma unroll
        for (int u = 0; u < 2; u++) {
            int idx = tid + u * 256;
            int r = idx >> 2;
            int c4 = (idx & 3) * 4;
            As[b][c4 + 0][r] = aR[u].x; As[b][c4 + 1][r] = aR[u].y;
            As[b][c4 + 2][r] = aR[u].z; As[b][c4 + 3][r] = aR[u].w;
        }
#pragma unroll
        for (int u = 0; u < NB; u++) {
            int idx = tid + u * 256;
            if (idx < BCH) {
                int r = idx / F4R;
                int c = (idx % F4R) * 4;
                *(float4*)&Bs[b][r][c] = bR[u];
            }
        }
    };

    int T = K >> 4;
    loadTile(0);
    storeTile(0);
    __syncthreads();

    for (int t = 0; t < T; t++) {
        int cur = t & 1;
        if (t + 1 < T) loadTile((t + 1) << 4);

#pragma unroll
        for (int kk = 0; kk < 16; kk++) {
            float a[8];
            *(float4*)&a[0] = *(const float4*)&As[cur][kk][tr * 8];
            *(float4*)&a[4] = *(const float4*)&As[cur][kk][tr * 8 + 4];
            ull bp[TN / 2];
#pragma unroll
            for (int j = 0; j < TN / 2; j++)
                bp[j] = *(const ull*)&Bs[cur][kk][tc * TN + 2 * j];
#pragma unroll
            for (int i = 0; i < 8; i++) {
                ull aa = pack2(a[i], a[i]);
#pragma unroll
                for (int j = 0; j < TN / 2; j++) ffma2(acc2[i][j], aa, bp[j]);
            }
        }
        if (t + 1 < T) {
            storeTile(cur ^ 1);
            __syncthreads();
        }
    }

#pragma unroll
    for (int i = 0; i < 8; i++) {
        int r = rowBase + tr * 8 + i;
        if (r >= M) continue;
        float o[TN];
#pragma unroll
        for (int j = 0; j < TN / 2; j++) unpack2(acc2[i][j], o[2 * j], o[2 * j + 1]);
        if (STOREH) {
            __half hh[TN];
#pragma unroll
            for (int j = 0; j < TN; j++) hh[j] = __float2half_rn(o[j]);
            char* dst = (char*)(g_h16 + (size_t)r * BN + tc * TN);
            if (TN == 8)      *(uint4*)dst = *(uint4*)hh;
            else if (TN == 4) *(uint2*)dst = *(uint2*)hh;
        } else {
            float* dst = g_h + (size_t)r * BN + tc * TN;
            if (TN == 8) {
                *(float4*)dst = *(float4*)&o[0];
                *(float4*)(dst + 4) = *(float4*)&o[4];
            } else if (TN == 4) {
                *(float4*)dst = *(float4*)&o[0];
            } else {
                *(float2*)dst = *(float2*)&o[0];
            }
        }
    }
}

// ---------------- fp16 gather: bufA = relu(H16[n]*invdeg + bias + sum norm*H16[src]) ----------------
// VEC = chunks of 8 halves (16B) per node row; each thread owns 8 features.
// Relu fused into the store (output feeds the next GEMM directly).
template <int VEC, int SHIFT>
__global__ void k_gather16(const float* __restrict__ bias) {
    int t = blockIdx.x * blockDim.x + threadIdx.x;
    if (t >= NN * VEC) return;
    int n = t >> SHIFT;
    int j = t & (VEC - 1);
    int beg = g_rowptr[n];
    int end = beg + g_count[n];
    const uint4* __restrict__ H = (const uint4*)g_h16;
    const ull* __restrict__ edge = g_edge;

    float acc[8];
    {
        float id = g_invdeg[n];
        uint4 hv = H[(size_t)n * VEC + j];
        const __half2* h2 = (const __half2*)&hv;
        const float* b = bias + j * 8;
#pragma unroll
        for (int q = 0; q < 4; q++) {
            float2 f = __half22float2(h2[q]);
            acc[2 * q + 0] = fmaf(f.x, id, b[2 * q + 0]);
            acc[2 * q + 1] = fmaf(f.y, id, b[2 * q + 1]);
        }
    }

    int k = beg;
    for (; k + 4 <= end; k += 4) {
        ull e0 = edge[k], e1 = edge[k + 1], e2 = edge[k + 2], e3 = edge[k + 3];
        uint4 v0 = H[(size_t)(unsigned int)e0 * VEC + j];
        uint4 v1 = H[(size_t)(unsigned int)e1 * VEC + j];
        uint4 v2 = H[(size_t)(unsigned int)e2 * VEC + j];
        uint4 v3 = H[(size_t)(unsigned int)e3 * VEC + j];
        float n0 = __uint_as_float((unsigned int)(e0 >> 32));
        float n1 = __uint_as_float((unsigned int)(e1 >> 32));
        float n2 = __uint_as_float((unsigned int)(e2 >> 32));
        float n3 = __uint_as_float((unsigned int)(e3 >> 32));
        const __half2* p0 = (const __half2*)&v0;
        const __half2* p1 = (const __half2*)&v1;
        const __half2* p2 = (const __half2*)&v2;
        const __half2* p3 = (const __half2*)&v3;
#pragma unroll
        for (int q = 0; q < 4; q++) {
            float2 f0 = __half22float2(p0[q]);
            float2 f1 = __half22float2(p1[q]);
            float2 f2 = __half22float2(p2[q]);
            float2 f3 = __half22float2(p3[q]);
            acc[2 * q + 0] = fmaf(n0, f0.x, acc[2 * q + 0]);
            acc[2 * q + 1] = fmaf(n0, f0.y, acc[2 * q + 1]);
            acc[2 * q + 0] = fmaf(n1, f1.x, acc[2 * q + 0]);
            acc[2 * q + 1] = fmaf(n1, f1.y, acc[2 * q + 1]);
            acc[2 * q + 0] = fmaf(n2, f2.x, acc[2 * q + 0]);
            acc[2 * q + 1] = fmaf(n2, f2.y, acc[2 * q + 1]);
            acc[2 * q + 0] = fmaf(n3, f3.x, acc[2 * q + 0]);
            acc[2 * q + 1] = fmaf(n3, f3.y, acc[2 * q + 1]);
        }
    }
    for (; k < end; k++) {
        ull e0 = edge[k];
        float nm = __uint_as_float((unsigned int)(e0 >> 32));
        uint4 v0 = H[(size_t)(unsigned int)e0 * VEC + j];
        const __half2* p0 = (const __half2*)&v0;
#pragma unroll
        for (int q = 0; q < 4; q++) {
            float2 f0 = __half22float2(p0[q]);
            acc[2 * q + 0] = fmaf(nm, f0.x, acc[2 * q + 0]);
            acc[2 * q + 1] = fmaf(nm, f0.y, acc[2 * q + 1]);
        }
    }

#pragma unroll
    for (int q = 0; q < 8; q++) acc[q] = fmaxf(acc[q], 0.f);   // relu fused here
    float* dst = g_bufA + ((size_t)n * VEC + j) * 8;
    *(float4*)dst = *(float4*)&acc[0];
    *(float4*)(dst + 4) = *(float4*)&acc[4];
}

// ---------------- layer-3 gather (fp32 H) fused with relu + mean-pool ----------------
__global__ void k_gather_pool(const float* __restrict__ bias,
                              const void* __restrict__ batch) {
    int t = blockIdx.x * blockDim.x + threadIdx.x;
    if (t >= NN * 8) return;
    int n = t >> 3;
    int j = t & 7;
    int beg = g_rowptr[n];
    int end = beg + g_count[n];
    const float4* __restrict__ H4 = (const float4*)g_h;
    const ull* __restrict__ edge = g_edge;

    float id = g_invdeg[n];
    float4 b = *(const float4*)(bias + j * 4);
    float4 hv = H4[(size_t)n * 8 + j];
    float4 acc;
    acc.x = fmaf(hv.x, id, b.x);
    acc.y = fmaf(hv.y, id, b.y);
    acc.z = fmaf(hv.z, id, b.z);
    acc.w = fmaf(hv.w, id, b.w);

    int k = beg;
    for (; k + 4 <= end; k += 4) {
        ull e0 = edge[k], e1 = edge[k + 1], e2 = edge[k + 2], e3 = edge[k + 3];
        float n0 = __uint_as_float((unsigned int)(e0 >> 32));
        float n1 = __uint_as_float((unsigned int)(e1 >> 32));
        float n2 = __uint_as_float((unsigned int)(e2 >> 32));
        float n3 = __uint_as_float((unsigned int)(e3 >> 32));
        float4 v0 = H4[(size_t)(unsigned int)e0 * 8 + j];
        float4 v1 = H4[(size_t)(unsigned int)e1 * 8 + j];
        float4 v2 = H4[(size_t)(unsigned int)e2 * 8 + j];
        float4 v3 = H4[(size_t)(unsigned int)e3 * 8 + j];
        acc.x = fmaf(n0, v0.x, acc.x); acc.y = fmaf(n0, v0.y, acc.y);
        acc.z = fmaf(n0, v0.z, acc.z); acc.w = fmaf(n0, v0.w, acc.w);
        acc.x = fmaf(n1, v1.x, acc.x); acc.y = fmaf(n1, v1.y, acc.y);
        acc.z = fmaf(n1, v1.z, acc.z); acc.w = fmaf(n1, v1.w, acc.w);
        acc.x = fmaf(n2, v2.x, acc.x); acc.y = fmaf(n2, v2.y, acc.y);
        acc.z = fmaf(n2, v2.z, acc.z); acc.w = fmaf(n2, v2.w, acc.w);
        acc.x = fmaf(n3, v3.x, acc.x); acc.y = fmaf(n3, v3.y, acc.y);
        acc.z = fmaf(n3, v3.z, acc.z); acc.w = fmaf(n3, v3.w, acc.w);
    }
    for (; k < end; k++) {
        ull e0 = edge[k];
        float nm = __uint_as_float((unsigned int)(e0 >> 32));
        float4 v = H4[(size_t)(unsigned int)e0 * 8 + j];
        acc.x = fmaf(nm, v.x, acc.x);
        acc.y = fmaf(nm, v.y, acc.y);
        acc.z = fmaf(nm, v.z, acc.z);
        acc.w = fmaf(nm, v.w, acc.w);
    }

    int g;
    if (g_oddOr == 0u) g = (int)((const long long*)batch)[n];
    else               g = ((const int*)batch)[n];
    float* p = &g_pool[g * 32 + j * 4];
    atomicAdd(p + 0, fmaxf(acc.x, 0.f));
    atomicAdd(p + 1, fmaxf(acc.y, 0.f));
    atomicAdd(p + 2, fmaxf(acc.z, 0.f));
    atomicAdd(p + 3, fmaxf(acc.w, 0.f));
    if (j == 0) atomicAdd(&g_cnt[g], 1.f);
}

// ---------------- head ----------------
__global__ void k_out(const float* __restrict__ Wl, const float* __restrict__ bl,
                      float* __restrict__ out) {
    __shared__ float pooled[32];
    int g = blockIdx.x;
    if (threadIdx.x < 32) {
        float c = g_cnt[g];
        pooled[threadIdx.x] = g_pool[g * 32 + threadIdx.x] / fmaxf(c, 1.f);
    }
    __syncthreads();
    int o = threadIdx.x;  // 768 threads
    float acc = bl[o];
#pragma unroll
    for (int c = 0; c < 32; c++) acc = fmaf(pooled[c], Wl[c * 768 + o], acc);
    out[(size_t)g * 768 + o] = acc;
}

// ---------------- launch (fork/join: CSR build || layer-1 GEMM) ----------------
extern "C" void kernel_launch(void* const* d_in, const int* in_sizes, int n_in,
                              void* d_out, int out_size) {
    const float* x = (const float*)d_in[0];
    const void* ei = d_in[1];
    const float* ea = (const float*)d_in[2];
    const void* batch = d_in[3];
    const float* W1 = (const float*)d_in[4];
    const float* b1 = (const float*)d_in[5];
    const float* W2 = (const float*)d_in[6];
    const float* b2 = (const float*)d_in[7];
    const float* W3 = (const float*)d_in[8];
    const float* b3 = (const float*)d_in[9];
    const float* Wl = (const float*)d_in[10];
    const float* bl = (const float*)d_in[11];
    float* out = (float*)d_out;

    static cudaStream_t s2 = nullptr;
    static cudaEvent_t evFork = nullptr, evJoin = nullptr;
    if (!s2) {
        cudaStreamCreateWithFlags(&s2, cudaStreamNonBlocking);
        cudaEventCreateWithFlags(&evFork, cudaEventDisableTiming);
        cudaEventCreateWithFlags(&evJoin, cudaEventDisableTiming);
    }
    cudaStream_t s0 = cudaStreamPerThread;

    // Fork: side stream runs layer-1 GEMM (depends only on x, W1) -> fp16 H.
    cudaEventRecord(evFork, s0);
    cudaStreamWaitEvent(s2, evFork, 0);
    {
        dim3 grid(1, (NN + 127) / 128);
        k_gemm<128, 8, 1><<<grid, 256, 0, s2>>>(x, 0, W1, NN, 128);
        cudaEventRecord(evJoin, s2);
    }

    // Main stream: CSR build chain.
    k_init<<<(NN + 255) / 256, 256, 0, s0>>>((const unsigned int*)ei);
    k_prep<<<512, 256, 0, s0>>>(ei, ea);
    k_scanA<<<NBLK, SCAN_BLK, 0, s0>>>();
    k_fill<<<(NE + 255) / 256, 256, 0, s0>>>(ea);

    // Join: gather-1 needs both H16 (s2) and CSR (s0).
    cudaStreamWaitEvent(s0, evJoin, 0);
    k_gather16<16, 4><<<(NN * 16 + 255) / 256, 256, 0, s0>>>(b1);

    // Layer 2: bufA(relu'd) @ W2 -> fp16 H; fp16 gather -> bufA (relu'd)
    {
        dim3 grid(1, (NN + 127) / 128);
        k_gemm<64, 4, 1><<<grid, 256, 0, s0>>>(nullptr, 1, W2, NN, 128);
        k_gather16<8, 3><<<(NN * 8 + 255) / 256, 256, 0, s0>>>(b2);
    }
    // Layer 3: bufA(relu'd) @ W3 -> fp32 H; fp32 gather fused with pool
    {
        dim3 grid(1, (NN + 127) / 128);
        k_gemm<32, 2, 0><<<grid, 256, 0, s0>>>(nullptr, 1, W3, NN, 64);
        k_gather_pool<<<(NN * 8 + 255) / 256, 256, 0, s0>>>(b3, batch);
    }
    k_out<<<NG, 768, 0, s0>>>(Wl, bl, out);
}

// round 15
// speedup vs baseline: 1.0755x; 1.0177x over previous
#include <cuda_runtime.h>
#include <cuda_fp16.h>
#include <cstdint>

#define NN 50000
#define NE 800000
#define NG 64
#define MAXF 128
#define SCAN_BLK 256
#define NBLK ((NN + SCAN_BLK - 1) / SCAN_BLK)   // 196

typedef unsigned long long ull;

// ---------------- scratch (device globals; no runtime allocation) ----------------
__device__ __align__(16) float g_bufA[NN * MAXF];
__device__ __align__(16) float g_h[NN * MAXF];        // fp32 H (layer 3)
__device__ __align__(16) __half g_h16[NN * MAXF];     // fp16 H (layers 1,2)
__device__ int   g_src[NE];
__device__ int   g_dst[NE];
__device__ ull   g_edge[NE];     // CSR-permuted (src | norm<<32)
__device__ int   g_count[NN];
__device__ int   g_rowptr[NN];   // bucket base (end = base + count)
__device__ int   g_fill[NN];
__device__ float g_deg[NN];
__device__ float g_dinv[NN];
__device__ float g_invdeg[NN];
__device__ __align__(16) float g_pool[NG * 32];
__device__ float g_cnt[NG];
__device__ unsigned int g_maxbits;
__device__ unsigned int g_oddOr;
__device__ int g_total;

// ---------------- packed f32x2 helpers ----------------
__device__ __forceinline__ ull pack2(float x, float y) {
    ull r; asm("mov.b64 %0, {%1,%2};" : "=l"(r) : "f"(x), "f"(y)); return r;
}
__device__ __forceinline__ void unpack2(ull v, float& x, float& y) {
    asm("mov.b64 {%0,%1}, %2;" : "=f"(x), "=f"(y) : "l"(v));
}
__device__ __forceinline__ void ffma2(ull& c, ull a, ull b) {
    asm("fma.rn.f32x2 %0, %1, %2, %0;" : "+l"(c) : "l"(a), "l"(b));
}

// ---------------- init + fast dtype detection ----------------
__global__ void k_init(const unsigned int* __restrict__ ei32) {
    int i = blockIdx.x * blockDim.x + threadIdx.x;
    if (i < NN) { g_deg[i] = 0.f; g_count[i] = 0; g_fill[i] = 0; }
    if (i < NG * 32) g_pool[i] = 0.f;
    if (i < NG) g_cnt[i] = 0.f;
    if (i == 0) { g_maxbits = 0u; g_oddOr = 0u; g_total = 0; }
    if (blockIdx.x == 0) {
        __syncthreads();
        unsigned int v = 0;
        for (int t = threadIdx.x; t < 8192; t += blockDim.x)
            v |= ei32[2 * t + 1];
#pragma unroll
        for (int o = 16; o; o >>= 1) v |= __shfl_xor_sync(0xffffffffu, v, o);
        if ((threadIdx.x & 31) == 0 && v) atomicOr(&g_oddOr, v);
    }
}

// ---------------- fused per-edge pass: decode, max(ea), raw deg, count ----------------
__global__ void k_prep(const void* __restrict__ ei, const float* __restrict__ ea) {
    bool is64 = (g_oddOr == 0u);
    const long long* p64 = (const long long*)ei;
    const int* p32 = (const int*)ei;
    float m = 0.f;
    for (int e = blockIdx.x * blockDim.x + threadIdx.x; e < NE;
         e += gridDim.x * blockDim.x) {
        int s, d;
        if (is64) { s = (int)p64[e]; d = (int)p64[NE + e]; }
        else      { s = p32[e];      d = p32[NE + e]; }
        g_src[e] = s;
        g_dst[e] = d;
        float a = ea[e];
        m = fmaxf(m, a);
        atomicAdd(&g_deg[d], a);
        atomicAdd(&g_count[d], 1);
    }
#pragma unroll
    for (int o = 16; o; o >>= 1) m = fmaxf(m, __shfl_xor_sync(0xffffffffu, m, o));
    if ((threadIdx.x & 31) == 0) atomicMax(&g_maxbits, __float_as_uint(m));
}

// ---------------- single-pass bucket allocation + node factors ----------------
__global__ void k_scanA() {
    __shared__ int wsum[SCAN_BLK / 32];
    __shared__ int sbase;
    int i = blockIdx.x * SCAN_BLK + threadIdx.x;
    int c = (i < NN) ? g_count[i] : 0;
    int lane = threadIdx.x & 31, wid = threadIdx.x >> 5;
    int v = c;
#pragma unroll
    for (int o = 1; o < 32; o <<= 1) {
        int u = __shfl_up_sync(0xffffffffu, v, o);
        if (lane >= o) v += u;
    }
    if (lane == 31) wsum[wid] = v;
    __syncthreads();
    if (wid == 0) {
        int w = (lane < SCAN_BLK / 32) ? wsum[lane] : 0;
#pragma unroll
        for (int o = 1; o < SCAN_BLK / 32; o <<= 1) {
            int u = __shfl_up_sync(0xffffffffu, w, o);
            if (lane >= o) w += u;
        }
        if (lane < SCAN_BLK / 32) wsum[lane] = w;
    }
    __syncthreads();
    if (threadIdx.x == 0) sbase = atomicAdd(&g_total, wsum[SCAN_BLK / 32 - 1]);
    __syncthreads();
    if (i < NN) {
        int excl = v - c + (wid > 0 ? wsum[wid - 1] : 0);
        g_rowptr[i] = sbase + excl;
        float invmax = 1.f / __uint_as_float(g_maxbits);
        float d = fmaf(g_deg[i], invmax, 1.f);
        g_dinv[i] = rsqrtf(d);
        g_invdeg[i] = 1.f / d;
    }
}

// ---------------- fill CSR: one packed 8B store per edge ----------------
__global__ void k_fill(const float* __restrict__ ea) {
    int e = blockIdx.x * blockDim.x + threadIdx.x;
    if (e >= NE) return;
    int s = g_src[e], d = g_dst[e];
    float invmax = 1.f / __uint_as_float(g_maxbits);
    float norm = g_dinv[s] * (ea[e] * invmax) * g_dinv[d];
    int pos = g_rowptr[d] + atomicAdd(&g_fill[d], 1);
    g_edge[pos] = (ull)(unsigned int)s | ((ull)__float_as_uint(norm) << 32);
}

// ---------------- 128xBN-tiled fp32 GEMM (layer 1 only; BM=128) ----------------
template <int BN, int TN, int STOREH>
__global__ void k_gemm(const float* __restrict__ Aext, int useBufA,
                       const float* __restrict__ W, int M, int K, int reluIn) {
    __shared__ float As[16][132];
    __shared__ float Bs[16][BN + 4];
    const float* A = useBufA ? g_bufA : Aext;

    int tid = threadIdx.x;
    int tr = tid >> 4;
    int tc = tid & 15;
    int rowBase = blockIdx.y * 128;

    ull acc2[8][TN / 2];
#pragma unroll
    for (int i = 0; i < 8; i++)
#pragma unroll
        for (int j = 0; j < TN / 2; j++) acc2[i][j] = 0ull;

    for (int kt = 0; kt < K; kt += 16) {
#pragma unroll
        for (int idx = tid; idx < 512; idx += 256) {
            int r = idx >> 2;
            int c4 = (idx & 3) * 4;
            int ar = rowBase + r;
            float4 v = make_float4(0.f, 0.f, 0.f, 0.f);
            if (ar < M) v = *(const float4*)(A + (size_t)ar * K + kt + c4);
            if (reluIn) {
                v.x = fmaxf(v.x, 0.f); v.y = fmaxf(v.y, 0.f);
                v.z = fmaxf(v.z, 0.f); v.w = fmaxf(v.w, 0.f);
            }
            As[c4 + 0][r] = v.x; As[c4 + 1][r] = v.y;
            As[c4 + 2][r] = v.z; As[c4 + 3][r] = v.w;
        }
        constexpr int F4R = BN / 4;
#pragma unroll
        for (int idx = tid; idx < 16 * F4R; idx += 256) {
            int r = idx / F4R;
            int c = (idx % F4R) * 4;
            float4 v = *(const float4*)(W + (size_t)(kt + r) * BN + c);
            *(float4*)&Bs[r][c] = v;
        }
        __syncthreads();

#pragma unroll
        for (int kk = 0; kk < 16; kk++) {
            float a[8];
            *(float4*)&a[0] = *(const float4*)&As[kk][tr * 8];
            *(float4*)&a[4] = *(const float4*)&As[kk][tr * 8 + 4];
            ull bp[TN / 2];
#pragma unroll
            for (int j = 0; j < TN / 2; j++)
                bp[j] = *(const ull*)&Bs[kk][tc * TN + 2 * j];
#pragma unroll
            for (int i = 0; i < 8; i++) {
                ull aa = pack2(a[i], a[i]);
#pragma unroll
                for (int j = 0; j < TN / 2; j++) ffma2(acc2[i][j], aa, bp[j]);
            }
        }
        __syncthreads();
    }

#pragma unroll
    for (int i = 0; i < 8; i++) {
        int r = rowBase + tr * 8 + i;
        if (r >= M) continue;
        float o[TN];
#pragma unroll
        for (int j = 0; j < TN / 2; j++) unpack2(acc2[i][j], o[2 * j], o[2 * j + 1]);
        if (STOREH) {
            __half hh[TN];
#pragma unroll
            for (int j = 0; j < TN; j++) hh[j] = __float2half_rn(o[j]);
            char* dst = (char*)(g_h16 + (size_t)r * BN + tc * TN);
            if (TN == 8)      *(uint4*)dst = *(uint4*)hh;
            else if (TN == 4) *(uint2*)dst = *(uint2*)hh;
        } else {
            float* dst = g_h + (size_t)r * BN + tc * TN;
            if (TN == 8) {
                *(float4*)dst = *(float4*)&o[0];
                *(float4*)(dst + 4) = *(float4*)&o[4];
            } else if (TN == 4) {
                *(float4*)dst = *(float4*)&o[0];
            } else {
                *(float2*)dst = *(float2*)&o[0];
            }
        }
    }
}

// ---------------- 64xBN-tiled fp32 GEMM (layers 2,3; 2x block count, high occupancy) ----------------
// 256 threads, thread tile 4 x TN. Grid = ceil(M/64) blocks.
template <int BN, int TN, int STOREH>
__global__ void k_gemm64(const float* __restrict__ Aext, int useBufA,
                         const float* __restrict__ W, int M, int K, int reluIn) {
    __shared__ float As[16][68];       // [k][m], 64 rows + pad (272B rows, 16B mult)
    __shared__ float Bs[16][BN + 4];
    const float* A = useBufA ? g_bufA : Aext;

    int tid = threadIdx.x;
    int tr = tid >> 4;        // 0..15 -> rows tr*4..tr*4+3
    int tc = tid & 15;        // cols tc*TN..
    int rowBase = blockIdx.y * 64;

    ull acc2[4][TN / 2];
#pragma unroll
    for (int i = 0; i < 4; i++)
#pragma unroll
        for (int j = 0; j < TN / 2; j++) acc2[i][j] = 0ull;

    for (int kt = 0; kt < K; kt += 16) {
        // A tile: 64x16 = 256 float4 chunks, one per thread
        {
            int r = tid >> 2;            // 0..63
            int c4 = (tid & 3) * 4;      // 0,4,8,12
            int ar = rowBase + r;
            float4 v = make_float4(0.f, 0.f, 0.f, 0.f);
            if (ar < M) v = *(const float4*)(A + (size_t)ar * K + kt + c4);
            if (reluIn) {
                v.x = fmaxf(v.x, 0.f); v.y = fmaxf(v.y, 0.f);
                v.z = fmaxf(v.z, 0.f); v.w = fmaxf(v.w, 0.f);
            }
            As[c4 + 0][r] = v.x; As[c4 + 1][r] = v.y;
            As[c4 + 2][r] = v.z; As[c4 + 3][r] = v.w;
        }
        constexpr int F4R = BN / 4;
#pragma unroll
        for (int idx = tid; idx < 16 * F4R; idx += 256) {
            int r = idx / F4R;
            int c = (idx % F4R) * 4;
            float4 v = *(const float4*)(W + (size_t)(kt + r) * BN + c);
            *(float4*)&Bs[r][c] = v;
        }
        __syncthreads();

#pragma unroll
        for (int kk = 0; kk < 16; kk++) {
            float a[4];
            *(float4*)&a[0] = *(const float4*)&As[kk][tr * 4];
            ull bp[TN / 2];
#pragma unroll
            for (int j = 0; j < TN / 2; j++)
                bp[j] = *(const ull*)&Bs[kk][tc * TN + 2 * j];
#pragma unroll
            for (int i = 0; i < 4; i++) {
                ull aa = pack2(a[i], a[i]);
#pragma unroll
                for (int j = 0; j < TN / 2; j++) ffma2(acc2[i][j], aa, bp[j]);
            }
        }
        __syncthreads();
    }

#pragma unroll
    for (int i = 0; i < 4; i++) {
        int r = rowBase + tr * 4 + i;
        if (r >= M) continue;
        float o[TN];
#pragma unroll
        for (int j = 0; j < TN / 2; j++) unpack2(acc2[i][j], o[2 * j], o[2 * j + 1]);
        if (STOREH) {
            __half hh[TN];
#pragma unroll
            for (int j = 0; j < TN; j++) hh[j] = __float2half_rn(o[j]);
            char* dst = (char*)(g_h16 + (size_t)r * BN + tc * TN);
            if (TN == 4)      *(uint2*)dst = *(uint2*)hh;
            else if (TN == 2) *(unsigned int*)dst = *(unsigned int*)hh;
        } else {
            float* dst = g_h + (size_t)r * BN + tc * TN;
            if (TN == 4) *(float4*)dst = *(float4*)&o[0];
            else         *(float2*)dst = *(float2*)&o[0];
        }
    }
}

// ---------------- fp16 gather: AGG(fp32) = H16[n]*invdeg + bias + sum norm*H16[src] ----------------
// VEC = chunks of 8 halves (16B) per node row; each thread owns 8 features.
template <int VEC, int SHIFT>
__global__ void k_gather16(const float* __restrict__ bias) {
    int t = blockIdx.x * blockDim.x + threadIdx.x;
    if (t >= NN * VEC) return;
    int n = t >> SHIFT;
    int j = t & (VEC - 1);
    int beg = g_rowptr[n];
    int end = beg + g_count[n];
    const uint4* __restrict__ H = (const uint4*)g_h16;
    const ull* __restrict__ edge = g_edge;

    float acc[8];
    {
        float id = g_invdeg[n];
        uint4 hv = H[(size_t)n * VEC + j];
        const __half2* h2 = (const __half2*)&hv;
        const float* b = bias + j * 8;
#pragma unroll
        for (int q = 0; q < 4; q++) {
            float2 f = __half22float2(h2[q]);
            acc[2 * q + 0] = fmaf(f.x, id, b[2 * q + 0]);
            acc[2 * q + 1] = fmaf(f.y, id, b[2 * q + 1]);
        }
    }

    int k = beg;
    for (; k + 4 <= end; k += 4) {
        ull e0 = edge[k], e1 = edge[k + 1], e2 = edge[k + 2], e3 = edge[k + 3];
        uint4 v0 = H[(size_t)(unsigned int)e0 * VEC + j];
        uint4 v1 = H[(size_t)(unsigned int)e1 * VEC + j];
        uint4 v2 = H[(size_t)(unsigned int)e2 * VEC + j];
        uint4 v3 = H[(size_t)(unsigned int)e3 * VEC + j];
        float n0 = __uint_as_float((unsigned int)(e0 >> 32));
        float n1 = __uint_as_float((unsigned int)(e1 >> 32));
        float n2 = __uint_as_float((unsigned int)(e2 >> 32));
        float n3 = __uint_as_float((unsigned int)(e3 >> 32));
        const __half2* p0 = (const __half2*)&v0;
        const __half2* p1 = (const __half2*)&v1;
        const __half2* p2 = (const __half2*)&v2;
        const __half2* p3 = (const __half2*)&v3;
#pragma unroll
        for (int q = 0; q < 4; q++) {
            float2 f0 = __half22float2(p0[q]);
            float2 f1 = __half22float2(p1[q]);
            float2 f2 = __half22float2(p2[q]);
            float2 f3 = __half22float2(p3[q]);
            acc[2 * q + 0] = fmaf(n0, f0.x, acc[2 * q + 0]);
            acc[2 * q + 1] = fmaf(n0, f0.y, acc[2 * q + 1]);
            acc[2 * q + 0] = fmaf(n1, f1.x, acc[2 * q + 0]);
            acc[2 * q + 1] = fmaf(n1, f1.y, acc[2 * q + 1]);
            acc[2 * q + 0] = fmaf(n2, f2.x, acc[2 * q + 0]);
            acc[2 * q + 1] = fmaf(n2, f2.y, acc[2 * q + 1]);
            acc[2 * q + 0] = fmaf(n3, f3.x, acc[2 * q + 0]);
            acc[2 * q + 1] = fmaf(n3, f3.y, acc[2 * q + 1]);
        }
    }
    for (; k < end; k++) {
        ull e0 = edge[k];
        float nm = __uint_as_float((unsigned int)(e0 >> 32));
        uint4 v0 = H[(size_t)(unsigned int)e0 * VEC + j];
        const __half2* p0 = (const __half2*)&v0;
#pragma unroll
        for (int q = 0; q < 4; q++) {
            float2 f0 = __half22float2(p0[q]);
            acc[2 * q + 0] = fmaf(nm, f0.x, acc[2 * q + 0]);
            acc[2 * q + 1] = fmaf(nm, f0.y, acc[2 * q + 1]);
        }
    }

    float* dst = g_bufA + ((size_t)n * VEC + j) * 8;
    *(float4*)dst = *(float4*)&acc[0];
    *(float4*)(dst + 4) = *(float4*)&acc[4];
}

// ---------------- layer-3 gather (fp32 H) fused with relu + mean-pool ----------------
__global__ void k_gather_pool(const float* __restrict__ bias,
                              const void* __restrict__ batch) {
    int t = blockIdx.x * blockDim.x + threadIdx.x;
    if (t >= NN * 8) return;
    int n = t >> 3;
    int j = t & 7;
    int beg = g_rowptr[n];
    int end = beg + g_count[n];
    const float4* __restrict__ H4 = (const float4*)g_h;
    const ull* __restrict__ edge = g_edge;

    float id = g_invdeg[n];
    float4 b = *(const float4*)(bias + j * 4);
    float4 hv = H4[(size_t)n * 8 + j];
    float4 acc;
    acc.x = fmaf(hv.x, id, b.x);
    acc.y = fmaf(hv.y, id, b.y);
    acc.z = fmaf(hv.z, id, b.z);
    acc.w = fmaf(hv.w, id, b.w);

    int k = beg;
    for (; k + 4 <= end; k += 4) {
        ull e0 = edge[k], e1 = edge[k + 1], e2 = edge[k + 2], e3 = edge[k + 3];
        float n0 = __uint_as_float((unsigned int)(e0 >> 32));
        float n1 = __uint_as_float((unsigned int)(e1 >> 32));
        float n2 = __uint_as_float((unsigned int)(e2 >> 32));
        float n3 = __uint_as_float((unsigned int)(e3 >> 32));
        float4 v0 = H4[(size_t)(unsigned int)e0 * 8 + j];
        float4 v1 = H4[(size_t)(unsigned int)e1 * 8 + j];
        float4 v2 = H4[(size_t)(unsigned int)e2 * 8 + j];
        float4 v3 = H4[(size_t)(unsigned int)e3 * 8 + j];
        acc.x = fmaf(n0, v0.x, acc.x); acc.y = fmaf(n0, v0.y, acc.y);
        acc.z = fmaf(n0, v0.z, acc.z); acc.w = fmaf(n0, v0.w, acc.w);
        acc.x = fmaf(n1, v1.x, acc.x); acc.y = fmaf(n1, v1.y, acc.y);
        acc.z = fmaf(n1, v1.z, acc.z); acc.w = fmaf(n1, v1.w, acc.w);
        acc.x = fmaf(n2, v2.x, acc.x); acc.y = fmaf(n2, v2.y, acc.y);
        acc.z = fmaf(n2, v2.z, acc.z); acc.w = fmaf(n2, v2.w, acc.w);
        acc.x = fmaf(n3, v3.x, acc.x); acc.y = fmaf(n3, v3.y, acc.y);
        acc.z = fmaf(n3, v3.z, acc.z); acc.w = fmaf(n3, v3.w, acc.w);
    }
    for (; k < end; k++) {
        ull e0 = edge[k];
        float nm = __uint_as_float((unsigned int)(e0 >> 32));
        float4 v = H4[(size_t)(unsigned int)e0 * 8 + j];
        acc.x = fmaf(nm, v.x, acc.x);
        acc.y = fmaf(nm, v.y, acc.y);
        acc.z = fmaf(nm, v.z, acc.z);
        acc.w = fmaf(nm, v.w, acc.w);
    }

    int g;
    if (g_oddOr == 0u) g = (int)((const long long*)batch)[n];
    else               g = ((const int*)batch)[n];
    float* p = &g_pool[g * 32 + j * 4];
    atomicAdd(p + 0, fmaxf(acc.x, 0.f));
    atomicAdd(p + 1, fmaxf(acc.y, 0.f));
    atomicAdd(p + 2, fmaxf(acc.z, 0.f));
    atomicAdd(p + 3, fmaxf(acc.w, 0.f));
    if (j == 0) atomicAdd(&g_cnt[g], 1.f);
}

// ---------------- head ----------------
__global__ void k_out(const float* __restrict__ Wl, const float* __restrict__ bl,
                      float* __restrict__ out) {
    __shared__ float pooled[32];
    int g = blockIdx.x;
    if (threadIdx.x < 32) {
        float c = g_cnt[g];
        pooled[threadIdx.x] = g_pool[g * 32 + threadIdx.x] / fmaxf(c, 1.f);
    }
    __syncthreads();
    int o = threadIdx.x;  // 768 threads
    float acc = bl[o];
#pragma unroll
    for (int c = 0; c < 32; c++) acc = fmaf(pooled[c], Wl[c * 768 + o], acc);
    out[(size_t)g * 768 + o] = acc;
}

// ---------------- launch (fork/join: CSR build || layer-1 GEMM) ----------------
extern "C" void kernel_launch(void* const* d_in, const int* in_sizes, int n_in,
                              void* d_out, int out_size) {
    const float* x = (const float*)d_in[0];
    const void* ei = d_in[1];
    const float* ea = (const float*)d_in[2];
    const void* batch = d_in[3];
    const float* W1 = (const float*)d_in[4];
    const float* b1 = (const float*)d_in[5];
    const float* W2 = (const float*)d_in[6];
    const float* b2 = (const float*)d_in[7];
    const float* W3 = (const float*)d_in[8];
    const float* b3 = (const float*)d_in[9];
    const float* Wl = (const float*)d_in[10];
    const float* bl = (const float*)d_in[11];
    float* out = (float*)d_out;

    static cudaStream_t s2 = nullptr;
    static cudaEvent_t evFork = nullptr, evJoin = nullptr;
    if (!s2) {
        cudaStreamCreateWithFlags(&s2, cudaStreamNonBlocking);
        cudaEventCreateWithFlags(&evFork, cudaEventDisableTiming);
        cudaEventCreateWithFlags(&evJoin, cudaEventDisableTiming);
    }
    cudaStream_t s0 = cudaStreamPerThread;

    // Fork: side stream runs layer-1 GEMM (depends only on x, W1) -> fp16 H.
    cudaEventRecord(evFork, s0);
    cudaStreamWaitEvent(s2, evFork, 0);
    {
        dim3 grid(1, (NN + 127) / 128);
        k_gemm<128, 8, 1><<<grid, 256, 0, s2>>>(x, 0, W1, NN, 128, /*relu=*/0);
        cudaEventRecord(evJoin, s2);
    }

    // Main stream: CSR build chain.
    k_init<<<(NN + 255) / 256, 256, 0, s0>>>((const unsigned int*)ei);
    k_prep<<<512, 256, 0, s0>>>(ei, ea);
    k_scanA<<<NBLK, SCAN_BLK, 0, s0>>>();
    k_fill<<<(NE + 255) / 256, 256, 0, s0>>>(ea);

    // Join: gather-1 needs both H16 (s2) and CSR (s0).
    cudaStreamWaitEvent(s0, evJoin, 0);
    k_gather16<16, 4><<<(NN * 16 + 255) / 256, 256, 0, s0>>>(b1);

    // Layer 2: relu(bufA) @ W2 -> fp16 H; fp16 gather -> bufA
    {
        dim3 grid(1, (NN + 63) / 64);
        k_gemm64<64, 4, 1><<<grid, 256, 0, s0>>>(nullptr, 1, W2, NN, 128, /*relu=*/1);
        k_gather16<8, 3><<<(NN * 8 + 255) / 256, 256, 0, s0>>>(b2);
    }
    // Layer 3: relu(bufA) @ W3 -> fp32 H; fp32 gather fused with pool
    {
        dim3 grid(1, (NN + 63) / 64);
        k_gemm64<32, 2, 0><<<grid, 256, 0, s0>>>(nullptr, 1, W3, NN, 64, /*relu=*/1);
        k_gather_pool<<<(NN * 8 + 255) / 256, 256, 0, s0>>>(b3, batch);
    }
    k_out<<<NG, 768, 0, s0>>>(Wl, bl, out);
}

// round 16
// speedup vs baseline: 1.1693x; 1.0873x over previous
#include <cuda_runtime.h>
#include <cuda_fp16.h>
#include <cstdint>

#define NN 50000
#define NE 800000
#define NG 64
#define MAXF 128
#define SCAN_BLK 256
#define NBLK ((NN + SCAN_BLK - 1) / SCAN_BLK)   // 196

typedef unsigned long long ull;

// ---------------- scratch (device globals; no runtime allocation) ----------------
__device__ __align__(16) float g_bufA[NN * MAXF];
__device__ __align__(16) float g_h[NN * MAXF];        // fp32 H (layer 3)
__device__ __align__(16) __half g_h16[NN * MAXF];     // fp16 H (layers 1,2)
__device__ ull   g_sd[NE];       // packed (src | dst<<32)
__device__ ull   g_edge[NE];     // CSR-permuted (src | norm<<32)
__device__ ull   g_dc[NN];       // packed (count<<32 | deg_fixedpoint)
__device__ int   g_count[NN];    // unpacked count (written by scanA, read by gathers)
__device__ int   g_rowptr[NN];   // bucket base; after fill: bucket END (base+count)
__device__ float g_dinv[NN];
__device__ float g_invdeg[NN];
__device__ __align__(16) float g_pool[NG * 32];
__device__ float g_cnt[NG];
__device__ unsigned int g_maxbits;
__device__ unsigned int g_oddOr;
__device__ int g_total;

#define DEG_SCALE 16777216.0f           // 2^24 fixed-point for deg accumulation
#define DEG_INV   (1.0f / 16777216.0f)

// ---------------- packed f32x2 helpers ----------------
__device__ __forceinline__ ull pack2(float x, float y) {
    ull r; asm("mov.b64 %0, {%1,%2};" : "=l"(r) : "f"(x), "f"(y)); return r;
}
__device__ __forceinline__ void unpack2(ull v, float& x, float& y) {
    asm("mov.b64 {%0,%1}, %2;" : "=f"(x), "=f"(y) : "l"(v));
}
__device__ __forceinline__ void ffma2(ull& c, ull a, ull b) {
    asm("fma.rn.f32x2 %0, %1, %2, %0;" : "+l"(c) : "l"(a), "l"(b));
}

// ---------------- init + fast dtype detection ----------------
__global__ void k_init(const unsigned int* __restrict__ ei32) {
    int i = blockIdx.x * blockDim.x + threadIdx.x;
    if (i < NN) g_dc[i] = 0ull;
    if (i < NG * 32) g_pool[i] = 0.f;
    if (i < NG) g_cnt[i] = 0.f;
    if (i == 0) { g_maxbits = 0u; g_oddOr = 0u; g_total = 0; }
    if (blockIdx.x == 0) {
        __syncthreads();
        unsigned int v = 0;
        for (int t = threadIdx.x; t < 8192; t += blockDim.x)
            v |= ei32[2 * t + 1];
#pragma unroll
        for (int o = 16; o; o >>= 1) v |= __shfl_xor_sync(0xffffffffu, v, o);
        if ((threadIdx.x & 31) == 0 && v) atomicOr(&g_oddOr, v);
    }
}

// ---------------- fused per-edge pass: decode, max(ea), packed deg+count ----------------
__global__ void k_prep(const void* __restrict__ ei, const float* __restrict__ ea) {
    bool is64 = (g_oddOr == 0u);
    const long long* p64 = (const long long*)ei;
    const int* p32 = (const int*)ei;
    float m = 0.f;
    for (int e = blockIdx.x * blockDim.x + threadIdx.x; e < NE;
         e += gridDim.x * blockDim.x) {
        int s, d;
        if (is64) { s = (int)p64[e]; d = (int)p64[NE + e]; }
        else      { s = p32[e];      d = p32[NE + e]; }
        g_sd[e] = (ull)(unsigned int)s | ((ull)(unsigned int)d << 32);
        float a = ea[e];
        m = fmaxf(m, a);
        // one atomic: count in high word, fixed-point deg in low word
        ull pkt = ((ull)1 << 32) | (ull)__float2uint_rn(a * DEG_SCALE);
        atomicAdd(&g_dc[d], pkt);
    }
#pragma unroll
    for (int o = 16; o; o >>= 1) m = fmaxf(m, __shfl_xor_sync(0xffffffffu, m, o));
    if ((threadIdx.x & 31) == 0) atomicMax(&g_maxbits, __float_as_uint(m));
}

// ---------------- single-pass bucket allocation + node factors ----------------
__global__ void k_scanA() {
    __shared__ int wsum[SCAN_BLK / 32];
    __shared__ int sbase;
    int i = blockIdx.x * SCAN_BLK + threadIdx.x;
    ull dc = (i < NN) ? g_dc[i] : 0ull;
    int c = (int)(dc >> 32);
    int lane = threadIdx.x & 31, wid = threadIdx.x >> 5;
    int v = c;
#pragma unroll
    for (int o = 1; o < 32; o <<= 1) {
        int u = __shfl_up_sync(0xffffffffu, v, o);
        if (lane >= o) v += u;
    }
    if (lane == 31) wsum[wid] = v;
    __syncthreads();
    if (wid == 0) {
        int w = (lane < SCAN_BLK / 32) ? wsum[lane] : 0;
#pragma unroll
        for (int o = 1; o < SCAN_BLK / 32; o <<= 1) {
            int u = __shfl_up_sync(0xffffffffu, w, o);
            if (lane >= o) w += u;
        }
        if (lane < SCAN_BLK / 32) wsum[lane] = w;
    }
    __syncthreads();
    if (threadIdx.x == 0) sbase = atomicAdd(&g_total, wsum[SCAN_BLK / 32 - 1]);
    __syncthreads();
    if (i < NN) {
        int excl = v - c + (wid > 0 ? wsum[wid - 1] : 0);
        g_rowptr[i] = sbase + excl;
        g_count[i] = c;
        float degraw = (float)(unsigned int)(dc & 0xffffffffu) * DEG_INV;
        float invmax = 1.f / __uint_as_float(g_maxbits);
        float d = fmaf(degraw, invmax, 1.f);
        g_dinv[i] = rsqrtf(d);
        g_invdeg[i] = 1.f / d;
    }
}

// ---------------- fill CSR: slot claimed by post-incrementing rowptr ----------------
// After this kernel, g_rowptr[n] == bucket END; gathers use beg = end - count[n].
__global__ void k_fill(const float* __restrict__ ea) {
    int e = blockIdx.x * blockDim.x + threadIdx.x;
    if (e >= NE) return;
    ull sd = g_sd[e];
    int s = (int)(unsigned int)sd;
    int d = (int)(sd >> 32);
    float invmax = 1.f / __uint_as_float(g_maxbits);
    float norm = g_dinv[s] * (ea[e] * invmax) * g_dinv[d];
    int pos = atomicAdd(&g_rowptr[d], 1);
    g_edge[pos] = (ull)(unsigned int)s | ((ull)__float_as_uint(norm) << 32);
}

// ---------------- 128xBN-tiled fp32 GEMM (R10 champion kernel) ----------------
template <int BN, int TN, int STOREH>
__global__ void k_gemm(const float* __restrict__ Aext, int useBufA,
                       const float* __restrict__ W, int M, int K, int reluIn) {
    __shared__ float As[16][132];
    __shared__ float Bs[16][BN + 4];
    const float* A = useBufA ? g_bufA : Aext;

    int tid = threadIdx.x;
    int tr = tid >> 4;
    int tc = tid & 15;
    int rowBase = blockIdx.y * 128;

    ull acc2[8][TN / 2];
#pragma unroll
    for (int i = 0; i < 8; i++)
#pragma unroll
        for (int j = 0; j < TN / 2; j++) acc2[i][j] = 0ull;

    for (int kt = 0; kt < K; kt += 16) {
#pragma unroll
        for (int idx = tid; idx < 512; idx += 256) {
            int r = idx >> 2;
            int c4 = (idx & 3) * 4;
            int ar = rowBase + r;
            float4 v = make_float4(0.f, 0.f, 0.f, 0.f);
            if (ar < M) v = *(const float4*)(A + (size_t)ar * K + kt + c4);
            if (reluIn) {
                v.x = fmaxf(v.x, 0.f); v.y = fmaxf(v.y, 0.f);
                v.z = fmaxf(v.z, 0.f); v.w = fmaxf(v.w, 0.f);
            }
            As[c4 + 0][r] = v.x; As[c4 + 1][r] = v.y;
            As[c4 + 2][r] = v.z; As[c4 + 3][r] = v.w;
        }
        constexpr int F4R = BN / 4;
#pragma unroll
        for (int idx = tid; idx < 16 * F4R; idx += 256) {
            int r = idx / F4R;
            int c = (idx % F4R) * 4;
            float4 v = *(const float4*)(W + (size_t)(kt + r) * BN + c);
            *(float4*)&Bs[r][c] = v;
        }
        __syncthreads();

#pragma unroll
        for (int kk = 0; kk < 16; kk++) {
            float a[8];
            *(float4*)&a[0] = *(const float4*)&As[kk][tr * 8];
            *(float4*)&a[4] = *(const float4*)&As[kk][tr * 8 + 4];
            ull bp[TN / 2];
#pragma unroll
            for (int j = 0; j < TN / 2; j++)
                bp[j] = *(const ull*)&Bs[kk][tc * TN + 2 * j];
#pragma unroll
            for (int i = 0; i < 8; i++) {
                ull aa = pack2(a[i], a[i]);
#pragma unroll
                for (int j = 0; j < TN / 2; j++) ffma2(acc2[i][j], aa, bp[j]);
            }
        }
        __syncthreads();
    }

#pragma unroll
    for (int i = 0; i < 8; i++) {
        int r = rowBase + tr * 8 + i;
        if (r >= M) continue;
        float o[TN];
#pragma unroll
        for (int j = 0; j < TN / 2; j++) unpack2(acc2[i][j], o[2 * j], o[2 * j + 1]);
        if (STOREH) {
            __half hh[TN];
#pragma unroll
            for (int j = 0; j < TN; j++) hh[j] = __float2half_rn(o[j]);
            char* dst = (char*)(g_h16 + (size_t)r * BN + tc * TN);
            if (TN == 8)      *(uint4*)dst = *(uint4*)hh;
            else if (TN == 4) *(uint2*)dst = *(uint2*)hh;
        } else {
            float* dst = g_h + (size_t)r * BN + tc * TN;
            if (TN == 8) {
                *(float4*)dst = *(float4*)&o[0];
                *(float4*)(dst + 4) = *(float4*)&o[4];
            } else if (TN == 4) {
                *(float4*)dst = *(float4*)&o[0];
            } else {
                *(float2*)dst = *(float2*)&o[0];
            }
        }
    }
}

// ---------------- fp16 gather: AGG(fp32) = H16[n]*invdeg + bias + sum norm*H16[src] ----------------
// VEC = chunks of 8 halves (16B) per node row; each thread owns 8 features.
template <int VEC, int SHIFT>
__global__ void k_gather16(const float* __restrict__ bias) {
    int t = blockIdx.x * blockDim.x + threadIdx.x;
    if (t >= NN * VEC) return;
    int n = t >> SHIFT;
    int j = t & (VEC - 1);
    int end = g_rowptr[n];            // after fill: bucket end
    int beg = end - g_count[n];
    const uint4* __restrict__ H = (const uint4*)g_h16;
    const ull* __restrict__ edge = g_edge;

    float acc[8];
    {
        float id = g_invdeg[n];
        uint4 hv = H[(size_t)n * VEC + j];
        const __half2* h2 = (const __half2*)&hv;
        const float* b = bias + j * 8;
#pragma unroll
        for (int q = 0; q < 4; q++) {
            float2 f = __half22float2(h2[q]);
            acc[2 * q + 0] = fmaf(f.x, id, b[2 * q + 0]);
            acc[2 * q + 1] = fmaf(f.y, id, b[2 * q + 1]);
        }
    }

    int k = beg;
    for (; k + 4 <= end; k += 4) {
        ull e0 = edge[k], e1 = edge[k + 1], e2 = edge[k + 2], e3 = edge[k + 3];
        uint4 v0 = H[(size_t)(unsigned int)e0 * VEC + j];
        uint4 v1 = H[(size_t)(unsigned int)e1 * VEC + j];
        uint4 v2 = H[(size_t)(unsigned int)e2 * VEC + j];
        uint4 v3 = H[(size_t)(unsigned int)e3 * VEC + j];
        float n0 = __uint_as_float((unsigned int)(e0 >> 32));
        float n1 = __uint_as_float((unsigned int)(e1 >> 32));
        float n2 = __uint_as_float((unsigned int)(e2 >> 32));
        float n3 = __uint_as_float((unsigned int)(e3 >> 32));
        const __half2* p0 = (const __half2*)&v0;
        const __half2* p1 = (const __half2*)&v1;
        const __half2* p2 = (const __half2*)&v2;
        const __half2* p3 = (const __half2*)&v3;
#pragma unroll
        for (int q = 0; q < 4; q++) {
            float2 f0 = __half22float2(p0[q]);
            float2 f1 = __half22float2(p1[q]);
            float2 f2 = __half22float2(p2[q]);
            float2 f3 = __half22float2(p3[q]);
            acc[2 * q + 0] = fmaf(n0, f0.x, acc[2 * q + 0]);
            acc[2 * q + 1] = fmaf(n0, f0.y, acc[2 * q + 1]);
            acc[2 * q + 0] = fmaf(n1, f1.x, acc[2 * q + 0]);
            acc[2 * q + 1] = fmaf(n1, f1.y, acc[2 * q + 1]);
            acc[2 * q + 0] = fmaf(n2, f2.x, acc[2 * q + 0]);
            acc[2 * q + 1] = fmaf(n2, f2.y, acc[2 * q + 1]);
            acc[2 * q + 0] = fmaf(n3, f3.x, acc[2 * q + 0]);
            acc[2 * q + 1] = fmaf(n3, f3.y, acc[2 * q + 1]);
        }
    }
    for (; k < end; k++) {
        ull e0 = edge[k];
        float nm = __uint_as_float((unsigned int)(e0 >> 32));
        uint4 v0 = H[(size_t)(unsigned int)e0 * VEC + j];
        const __half2* p0 = (const __half2*)&v0;
#pragma unroll
        for (int q = 0; q < 4; q++) {
            float2 f0 = __half22float2(p0[q]);
            acc[2 * q + 0] = fmaf(nm, f0.x, acc[2 * q + 0]);
            acc[2 * q + 1] = fmaf(nm, f0.y, acc[2 * q + 1]);
        }
    }

    float* dst = g_bufA + ((size_t)n * VEC + j) * 8;
    *(float4*)dst = *(float4*)&acc[0];
    *(float4*)(dst + 4) = *(float4*)&acc[4];
}

// ---------------- layer-3 gather (fp32 H) fused with relu + mean-pool ----------------
__global__ void k_gather_pool(const float* __restrict__ bias,
                              const void* __restrict__ batch) {
    int t = blockIdx.x * blockDim.x + threadIdx.x;
    if (t >= NN * 8) return;
    int n = t >> 3;
    int j = t & 7;
    int end = g_rowptr[n];
    int beg = end - g_count[n];
    const float4* __restrict__ H4 = (const float4*)g_h;
    const ull* __restrict__ edge = g_edge;

    float id = g_invdeg[n];
    float4 b = *(const float4*)(bias + j * 4);
    float4 hv = H4[(size_t)n * 8 + j];
    float4 acc;
    acc.x = fmaf(hv.x, id, b.x);
    acc.y = fmaf(hv.y, id, b.y);
    acc.z = fmaf(hv.z, id, b.z);
    acc.w = fmaf(hv.w, id, b.w);

    int k = beg;
    for (; k + 4 <= end; k += 4) {
        ull e0 = edge[k], e1 = edge[k + 1], e2 = edge[k + 2], e3 = edge[k + 3];
        float n0 = __uint_as_float((unsigned int)(e0 >> 32));
        float n1 = __uint_as_float((unsigned int)(e1 >> 32));
        float n2 = __uint_as_float((unsigned int)(e2 >> 32));
        float n3 = __uint_as_float((unsigned int)(e3 >> 32));
        float4 v0 = H4[(size_t)(unsigned int)e0 * 8 + j];
        float4 v1 = H4[(size_t)(unsigned int)e1 * 8 + j];
        float4 v2 = H4[(size_t)(unsigned int)e2 * 8 + j];
        float4 v3 = H4[(size_t)(unsigned int)e3 * 8 + j];
        acc.x = fmaf(n0, v0.x, acc.x); acc.y = fmaf(n0, v0.y, acc.y);
        acc.z = fmaf(n0, v0.z, acc.z); acc.w = fmaf(n0, v0.w, acc.w);
        acc.x = fmaf(n1, v1.x, acc.x); acc.y = fmaf(n1, v1.y, acc.y);
        acc.z = fmaf(n1, v1.z, acc.z); acc.w = fmaf(n1, v1.w, acc.w);
        acc.x = fmaf(n2, v2.x, acc.x); acc.y = fmaf(n2, v2.y, acc.y);
        acc.z = fmaf(n2, v2.z, acc.z); acc.w = fmaf(n2, v2.w, acc.w);
        acc.x = fmaf(n3, v3.x, acc.x); acc.y = fmaf(n3, v3.y, acc.y);
        acc.z = fmaf(n3, v3.z, acc.z); acc.w = fmaf(n3, v3.w, acc.w);
    }
    for (; k < end; k++) {
        ull e0 = edge[k];
        float nm = __uint_as_float((unsigned int)(e0 >> 32));
        float4 v = H4[(size_t)(unsigned int)e0 * 8 + j];
        acc.x = fmaf(nm, v.x, acc.x);
        acc.y = fmaf(nm, v.y, acc.y);
        acc.z = fmaf(nm, v.z, acc.z);
        acc.w = fmaf(nm, v.w, acc.w);
    }

    int g;
    if (g_oddOr == 0u) g = (int)((const long long*)batch)[n];
    else               g = ((const int*)batch)[n];
    float* p = &g_pool[g * 32 + j * 4];
    atomicAdd(p + 0, fmaxf(acc.x, 0.f));
    atomicAdd(p + 1, fmaxf(acc.y, 0.f));
    atomicAdd(p + 2, fmaxf(acc.z, 0.f));
    atomicAdd(p + 3, fmaxf(acc.w, 0.f));
    if (j == 0) atomicAdd(&g_cnt[g], 1.f);
}

// ---------------- head ----------------
__global__ void k_out(const float* __restrict__ Wl, const float* __restrict__ bl,
                      float* __restrict__ out) {
    __shared__ float pooled[32];
    int g = blockIdx.x;
    if (threadIdx.x < 32) {
        float c = g_cnt[g];
        pooled[threadIdx.x] = g_pool[g * 32 + threadIdx.x] / fmaxf(c, 1.f);
    }
    __syncthreads();
    int o = threadIdx.x;  // 768 threads
    float acc = bl[o];
#pragma unroll
    for (int c = 0; c < 32; c++) acc = fmaf(pooled[c], Wl[c * 768 + o], acc);
    out[(size_t)g * 768 + o] = acc;
}

// ---------------- launch (fork/join: CSR build || layer-1 GEMM) ----------------
extern "C" void kernel_launch(void* const* d_in, const int* in_sizes, int n_in,
                              void* d_out, int out_size) {
    const float* x = (const float*)d_in[0];
    const void* ei = d_in[1];
    const float* ea = (const float*)d_in[2];
    const void* batch = d_in[3];
    const float* W1 = (const float*)d_in[4];
    const float* b1 = (const float*)d_in[5];
    const float* W2 = (const float*)d_in[6];
    const float* b2 = (const float*)d_in[7];
    const float* W3 = (const float*)d_in[8];
    const float* b3 = (const float*)d_in[9];
    const float* Wl = (const float*)d_in[10];
    const float* bl = (const float*)d_in[11];
    float* out = (float*)d_out;

    static cudaStream_t s2 = nullptr;
    static cudaEvent_t evFork = nullptr, evJoin = nullptr;
    if (!s2) {
        cudaStreamCreateWithFlags(&s2, cudaStreamNonBlocking);
        cudaEventCreateWithFlags(&evFork, cudaEventDisableTiming);
        cudaEventCreateWithFlags(&evJoin, cudaEventDisableTiming);
    }
    cudaStream_t s0 = cudaStreamPerThread;

    // Fork: side stream runs layer-1 GEMM (depends only on x, W1) -> fp16 H.
    cudaEventRecord(evFork, s0);
    cudaStreamWaitEvent(s2, evFork, 0);
    {
        dim3 grid(1, (NN + 127) / 128);
        k_gemm<128, 8, 1><<<grid, 256, 0, s2>>>(x, 0, W1, NN, 128, /*relu=*/0);
        cudaEventRecord(evJoin, s2);
    }

    // Main stream: CSR build chain.
    k_init<<<(NN + 255) / 256, 256, 0, s0>>>((const unsigned int*)ei);
    k_prep<<<512, 256, 0, s0>>>(ei, ea);
    k_scanA<<<NBLK, SCAN_BLK, 0, s0>>>();
    k_fill<<<(NE + 255) / 256, 256, 0, s0>>>(ea);

    // Join: gather-1 needs both H16 (s2) and CSR (s0).
    cudaStreamWaitEvent(s0, evJoin, 0);
    k_gather16<16, 4><<<(NN * 16 + 255) / 256, 256, 0, s0>>>(b1);

    // Layer 2: relu(bufA) @ W2 -> fp16 H; fp16 gather -> bufA
    {
        dim3 grid(1, (NN + 127) / 128);
        k_gemm<64, 4, 1><<<grid, 256, 0, s0>>>(nullptr, 1, W2, NN, 128, /*relu=*/1);
        k_gather16<8, 3><<<(NN * 8 + 255) / 256, 256, 0, s0>>>(b2);
    }
    // Layer 3: relu(bufA) @ W3 -> fp32 H; fp32 gather fused with pool
    {
        dim3 grid(1, (NN + 127) / 128);
        k_gemm<32, 2, 0><<<grid, 256, 0, s0>>>(nullptr, 1, W3, NN, 64, /*relu=*/1);
        k_gather_pool<<<(NN * 8 + 255) / 256, 256, 0, s0>>>(b3, batch);
    }
    k_out<<<NG, 768, 0, s0>>>(Wl, bl, out);
}